// round 8
// baseline (speedup 1.0000x reference)
#include <cuda_runtime.h>
#include <cstdint>
#include <math.h>

// Problem constants
#define Bn  4
#define Hn  128
#define Wn  128
#define HWn (Hn*Wn)

// Intermediate scratch (device globals: no allocation allowed)
__device__ float g_off1[Bn*18*HWn];
__device__ float g_mask1[Bn*9*HWn];
__device__ float g_h   [Bn*64*HWn];
__device__ float g_off2[Bn*18*HWn];
__device__ float g_mask2[Bn*9*HWn];
__device__ float g_w1t[3*9*64];     // w1 transposed: [c][k][o]
__device__ float g_w2t[64*9*128];   // w2 transposed: [c][k][o]

// ---------------------------------------------------------------------------
// f32x2 helpers (used in deform2 GEMM only — proven win there, loser in offmask)
// ---------------------------------------------------------------------------
__device__ __forceinline__ unsigned long long f32x2_dup(float w){
    unsigned long long d;
    asm("mov.b64 %0, {%1, %1};" : "=l"(d) : "r"(__float_as_uint(w)));
    return d;
}
__device__ __forceinline__ void f32x2_unpack(unsigned long long v, float& lo, float& hi){
    unsigned int a, b;
    asm("mov.b64 {%0, %1}, %2;" : "=r"(a), "=r"(b) : "l"(v));
    lo = __uint_as_float(a); hi = __uint_as_float(b);
}
__device__ __forceinline__ void fma_f32x2(unsigned long long& acc,
                                          unsigned long long a,
                                          unsigned long long b){
    asm("fma.rn.f32x2 %0, %1, %2, %0;" : "+l"(acc) : "l"(a), "l"(b));
}
__device__ __forceinline__ void cp_async16(unsigned int s, const void* g){
    asm volatile("cp.async.cg.shared.global [%0], [%1], 16;" :: "r"(s), "l"(g));
}
__device__ __forceinline__ void cp_commit(){
    asm volatile("cp.async.commit_group;");
}
__device__ __forceinline__ void cp_wait0(){
    asm volatile("cp.async.wait_group 0;");
}

// ---------------------------------------------------------------------------
// One-time weight transpose: w*t[(c*9+k)*COUT + o] = w[(o*CIN+c)*9 + k]
// ---------------------------------------------------------------------------
__global__ void wtrans_kernel(const float* __restrict__ w1, const float* __restrict__ w2,
                              float* __restrict__ w1t, float* __restrict__ w2t)
{
    int i = blockIdx.x*256 + threadIdx.x;
    if (i < 3*9*64){
        int o = i & 63; int ck = i >> 6; int c = ck/9, k = ck - 9*c;
        w1t[i] = w1[(o*3 + c)*9 + k];
    }
    if (i < 64*9*128){
        int o = i & 127; int ck = i >> 7; int c = ck/9, k = ck - 9*c;
        w2t[i] = w2[(o*64 + c)*9 + k];
    }
}

// ---------------------------------------------------------------------------
// offset/mask conv v4: m-split occupancy fix.
// 512 threads/block: halves mh=0/1 each compute 16 of the 32-padded outputs
// for the full 16x16 tile. Scalar FFMA inner loop (f32x2 lost twice here).
// 2 blocks/SM (forced via launch_bounds) -> grid 256 in ONE wave, ~32 warps/SM.
// ---------------------------------------------------------------------------
template<int CIN, int CC>
__global__ __launch_bounds__(512, 2)
void offmask_kernel(const float* __restrict__ in,
                    const float* __restrict__ w_off, const float* __restrict__ b_off,
                    const float* __restrict__ w_mask, const float* __restrict__ b_mask,
                    float* __restrict__ off_out, float* __restrict__ mask_out)
{
    constexpr int NCH = CIN/CC;
    __shared__ float tile[CC][18][18];
    __shared__ __align__(16) float wsh[CC*9][32];   // m padded 27->32

    int tid = threadIdx.x;
    int mh  = tid >> 8;        // 0/1: which 16-output half
    int wg  = tid & 255;
    int blk = blockIdx.x;
    int bx = blk & 7;
    int by = (blk >> 3) & 7;
    int b  = blk >> 6;
    int h0 = by*16, w0 = bx*16;
    int ty = wg >> 4, tx = wg & 15;

    float acc[16];
    #pragma unroll
    for (int i=0;i<16;i++) acc[i] = 0.f;

    for (int ch=0; ch<NCH; ch++){
        int c0 = ch*CC;
        // input tile with zero halo (512 threads cooperative)
        for (int i=tid; i<CC*18*18; i+=512){
            int c = i/(18*18); int r = (i/18)%18; int col = i%18;
            int gy = h0-1+r, gx = w0-1+col;
            float v = 0.f;
            if (gy>=0 && gy<Hn && gx>=0 && gx<Wn)
                v = in[((b*CIN + c0+c)*Hn + gy)*Wn + gx];
            tile[c][r][col] = v;
        }
        // weights m-fastest, 32-padded (zeros for m>=27)
        for (int i=tid; i<CC*9*32; i+=512){
            int ck = i >> 5; int m = i & 31;
            int c = ck/9, k = ck - c*9;
            float v = 0.f;
            if (m < 18)      v = __ldg(&w_off [(m*CIN + c0+c)*9 + k]);
            else if (m < 27) v = __ldg(&w_mask[((m-18)*CIN + c0+c)*9 + k]);
            wsh[ck][m] = v;
        }
        __syncthreads();
        #pragma unroll
        for (int c=0;c<CC;c++){
            float nb[9];
            #pragma unroll
            for (int ky=0;ky<3;ky++)
                #pragma unroll
                for (int kx=0;kx<3;kx++)
                    nb[ky*3+kx] = tile[c][ty+ky][tx+kx];
            #pragma unroll
            for (int k=0;k<9;k++){
                float v = nb[k];
                const float4* wp = (const float4*)&wsh[c*9+k][mh*16];
                #pragma unroll
                for (int jg=0; jg<4; jg++){
                    float4 wv = wp[jg];
                    acc[jg*4+0] = fmaf(v, wv.x, acc[jg*4+0]);
                    acc[jg*4+1] = fmaf(v, wv.y, acc[jg*4+1]);
                    acc[jg*4+2] = fmaf(v, wv.z, acc[jg*4+2]);
                    acc[jg*4+3] = fmaf(v, wv.w, acc[jg*4+3]);
                }
            }
        }
        __syncthreads();
    }

    // Epilogue: each half writes its own m-range. Coalesced over hw.
    int hw = (h0+ty)*Wn + (w0+tx);
    #pragma unroll
    for (int j=0;j<16;j++){
        int m = mh*16 + j;
        if (m < 18)
            off_out[(b*18+m)*HWn + hw] = acc[j] + b_off[m];
        else if (m < 27)
            mask_out[(b*9+m-18)*HWn + hw] =
                1.f/(1.f + expf(-(acc[j] + b_mask[m-18])));
    }
}

// ---------------------------------------------------------------------------
// Layer-1 deformable conv (CIN=3): staging uses pre-transposed weights.
// ---------------------------------------------------------------------------
template<int CIN, int COUT, int CC, int OCT>
__global__ __launch_bounds__(256)
void deform_kernel(const float* __restrict__ in,
                   const float* __restrict__ off, const float* __restrict__ mask,
                   const float* __restrict__ wt, const float* __restrict__ bias,
                   float* __restrict__ out)
{
    constexpr int TP  = 64;
    constexpr int OG  = COUT/OCT;
    constexpr int NPG = 256/OG;
    constexpr int PXT = TP/NPG;
    constexpr int NCH = CIN/CC;
    constexpr int PARAMF = 5*9*TP;
    constexpr int WF = CC*9*COUT;
    constexpr int SF = 9*CC*TP;
    constexpr int MAINF = PARAMF + WF + SF;
    constexpr int OUTF  = COUT*TP;
    constexpr int SMEMF = (MAINF > OUTF) ? MAINF : OUTF;
    __shared__ __align__(16) float buf[SMEMF];

    int*   y0_sh  = (int*)buf;
    int*   x0_sh  = (int*)(buf + 9*TP);
    float* wy1_sh = buf + 2*9*TP;
    float* wx1_sh = buf + 3*9*TP;
    float* mm_sh  = buf + 4*9*TP;
    float* w_sh   = buf + PARAMF;
    float* samp_sh= buf + PARAMF + WF;

    int tid  = threadIdx.x;
    int base = blockIdx.x * TP;
    int b    = base / HWn;
    int rem  = base - b*HWn;
    int h    = rem / Wn;
    int w0   = rem - h*Wn;

    for (int s=tid; s<9*TP; s+=256){
        int p = s & (TP-1); int k = s/TP;
        int wpix = w0 + p;
        int hw = h*Wn + wpix;
        float dy = off[(b*18 + 2*k  )*HWn + hw];
        float dx = off[(b*18 + 2*k+1)*HWn + hw];
        float mm = mask[(b*9 + k)*HWn + hw];
        int ky = k/3, kx = k - ky*3;
        float py = dy + (float)(h - 1 + ky);
        float px = dx + (float)(wpix - 1 + kx);
        float fy = floorf(py), fx = floorf(px);
        y0_sh[s]  = (int)fy;
        x0_sh[s]  = (int)fx;
        wy1_sh[s] = py - fy;
        wx1_sh[s] = px - fx;
        mm_sh[s]  = mm;
    }

    float acc[PXT][OCT];
    #pragma unroll
    for (int i=0;i<PXT;i++)
        #pragma unroll
        for (int j=0;j<OCT;j++) acc[i][j] = 0.f;

    int og = tid % OG;
    int pg = tid / OG;

    __syncthreads();

    for (int ch=0; ch<NCH; ch++){
        int c0 = ch*CC;
        for (int i=tid; i<WF; i+=256)
            w_sh[i] = wt[ch*WF + i];
        for (int s=tid; s<9*CC*TP; s+=256){
            int p = s & (TP-1); int cc = (s/TP)%CC; int k = s/(TP*CC);
            int kp = k*TP + p;
            int y0 = y0_sh[kp], x0 = x0_sh[kp];
            float wy1 = wy1_sh[kp], wx1 = wx1_sh[kp];
            float wy0 = 1.f-wy1, wx0 = 1.f-wx1;
            const float* cp = in + (size_t)(b*CIN + c0+cc)*HWn;
            int y1 = y0+1, x1 = x0+1;
            bool vy0 = (unsigned)y0 < (unsigned)Hn;
            bool vy1 = (unsigned)y1 < (unsigned)Hn;
            bool vx0 = (unsigned)x0 < (unsigned)Wn;
            bool vx1 = (unsigned)x1 < (unsigned)Wn;
            float v = 0.f;
            if (vy0 && vx0) v = fmaf(cp[y0*Wn+x0], wy0*wx0, v);
            if (vy0 && vx1) v = fmaf(cp[y0*Wn+x1], wy0*wx1, v);
            if (vy1 && vx0) v = fmaf(cp[y1*Wn+x0], wy1*wx0, v);
            if (vy1 && vx1) v = fmaf(cp[y1*Wn+x1], wy1*wx1, v);
            samp_sh[(k*CC+cc)*TP + p] = v * mm_sh[kp];
        }
        __syncthreads();
        #pragma unroll
        for (int c=0;c<CC;c++){
            #pragma unroll
            for (int k=0;k<9;k++){
                float wv[OCT];
                const float* wp = w_sh + (c*9+k)*COUT + og*OCT;
                if constexpr (OCT == 4){
                    float4 t = *(const float4*)wp;
                    wv[0]=t.x; wv[1]=t.y; wv[2]=t.z; wv[3]=t.w;
                } else {
                    float2 t = *(const float2*)wp;
                    wv[0]=t.x; wv[1]=t.y;
                }
                const float* sp = samp_sh + (k*CC+c)*TP + pg*PXT;
                float4 s0 = *(const float4*)sp;
                float4 s1 = *(const float4*)(sp+4);
                float sv[8] = {s0.x,s0.y,s0.z,s0.w,s1.x,s1.y,s1.z,s1.w};
                #pragma unroll
                for (int px=0; px<PXT; px++)
                    #pragma unroll
                    for (int oc=0; oc<OCT; oc++)
                        acc[px][oc] = fmaf(sv[px], wv[oc], acc[px][oc]);
            }
        }
        __syncthreads();
    }

    float* out_sh = buf;
    #pragma unroll
    for (int px=0; px<PXT; px++)
        #pragma unroll
        for (int oc=0; oc<OCT; oc++)
            out_sh[(og*OCT+oc)*TP + pg*PXT + px] = acc[px][oc];
    __syncthreads();
    for (int i=tid; i<OUTF; i+=256){
        int o = i/TP; int p = i & (TP-1);
        float v = out_sh[i] + bias[o];
        out[((size_t)b*COUT + o)*HWn + rem + p] = fmaxf(v, 0.f);
    }
}

// ---------------------------------------------------------------------------
// Layer-2 deformable conv v3:
//   pre-transposed weights via cp.async, double-buffered, one barrier/chunk,
//   f32x2 GEMM with pixel-paired accumulators.
// ---------------------------------------------------------------------------
template<int CIN, int COUT>
__global__ __launch_bounds__(256, 2)
void deform2_kernel(const float* __restrict__ in,
                    const float* __restrict__ off, const float* __restrict__ mask,
                    const float* __restrict__ wt, const float* __restrict__ bias,
                    float* __restrict__ out)
{
    constexpr int TP  = 64;
    constexpr int CC  = 4;
    constexpr int NCH = CIN/CC;     // 16
    constexpr int OCT = 4;
    constexpr int PXT = 8;
    constexpr int KP  = 9*TP;       // 576
    constexpr int WF  = CC*9*COUT;  // 4608
    constexpr int SF  = 9*CC*TP;    // 2304
    constexpr int ELEMS = 9;
    extern __shared__ __align__(16) float smem[];

    int*   off_sh = (int*)smem;               // [4][KP]
    float* wgt_sh = smem + 4*KP;              // [4][KP]
    float* w_shA  = smem + 8*KP;              // [WF] x2
    float* w_shB  = w_shA + WF;
    float* sampA  = w_shB + WF;               // [SF] x2
    float* sampB  = sampA + SF;

    int tid  = threadIdx.x;
    int base = blockIdx.x * TP;
    int b    = base / HWn;
    int rem  = base - b*HWn;
    int h    = rem / Wn;
    int w0   = rem - h*Wn;

    for (int s=tid; s<KP; s+=256){
        int p = s & 63, k = s >> 6;
        int wpix = w0 + p;
        int hw = h*Wn + wpix;
        float dy = off[(b*18 + 2*k  )*HWn + hw];
        float dx = off[(b*18 + 2*k+1)*HWn + hw];
        float mm = mask[(b*9 + k)*HWn + hw];
        int ky = k/3, kx = k - ky*3;
        float py = dy + (float)(h - 1 + ky);
        float px = dx + (float)(wpix - 1 + kx);
        float fy = floorf(py), fx = floorf(px);
        int y0 = (int)fy, x0 = (int)fx;
        int y1 = y0+1, x1 = x0+1;
        float wy1 = py - fy, wx1 = px - fx;
        float wy0 = 1.f - wy1, wx0 = 1.f - wx1;
        bool vy0 = (unsigned)y0 < (unsigned)Hn;
        bool vy1 = (unsigned)y1 < (unsigned)Hn;
        bool vx0 = (unsigned)x0 < (unsigned)Wn;
        bool vx1 = (unsigned)x1 < (unsigned)Wn;
        int y0c = min(max(y0,0),Hn-1), y1c = min(max(y1,0),Hn-1);
        int x0c = min(max(x0,0),Wn-1), x1c = min(max(x1,0),Wn-1);
        off_sh[0*KP+s] = y0c*Wn + x0c;  wgt_sh[0*KP+s] = (vy0&&vx0) ? wy0*wx0*mm : 0.f;
        off_sh[1*KP+s] = y0c*Wn + x1c;  wgt_sh[1*KP+s] = (vy0&&vx1) ? wy0*wx1*mm : 0.f;
        off_sh[2*KP+s] = y1c*Wn + x0c;  wgt_sh[2*KP+s] = (vy1&&vx0) ? wy1*wx0*mm : 0.f;
        off_sh[3*KP+s] = y1c*Wn + x1c;  wgt_sh[3*KP+s] = (vy1&&vx1) ? wy1*wx1*mm : 0.f;
    }
    __syncthreads();

    const float* in_b = in + (size_t)b*CIN*HWn;
    int og = tid & 31;
    int pg = tid >> 5;

    unsigned long long acc[PXT/2][OCT];
    #pragma unroll
    for (int i=0;i<PXT/2;i++)
        #pragma unroll
        for (int j=0;j<OCT;j++) acc[i][j] = 0ULL;

    float pv[ELEMS][4];

    auto stage_w = [&](int ch, float* dst){
        unsigned int d = (unsigned int)__cvta_generic_to_shared(dst);
        const float4* src = (const float4*)(wt + ch*WF);
        #pragma unroll
        for (int j=0;j<5;j++){
            int i = tid + j*256;
            if (i < WF/4) cp_async16(d + i*16, src + i);
        }
        cp_commit();
    };
    auto prefetch = [&](int ch){
        int c0 = ch*CC;
        #pragma unroll
        for (int e=0;e<ELEMS;e++){
            int s = tid + e*256;
            int p = s & 63, c = (s>>6)&3, k = s>>8;
            int kp = (k<<6) + p;
            const float* cp = in_b + (size_t)(c0+c)*HWn;
            pv[e][0] = __ldg(cp + off_sh[0*KP+kp]);
            pv[e][1] = __ldg(cp + off_sh[1*KP+kp]);
            pv[e][2] = __ldg(cp + off_sh[2*KP+kp]);
            pv[e][3] = __ldg(cp + off_sh[3*KP+kp]);
        }
    };
    auto combine_store = [&](float* dst){
        #pragma unroll
        for (int e=0;e<ELEMS;e++){
            int s = tid + e*256;
            int p = s & 63, c = (s>>6)&3, k = s>>8;
            int kp = (k<<6) + p;
            float v = pv[e][0]*wgt_sh[0*KP+kp]
                    + pv[e][1]*wgt_sh[1*KP+kp]
                    + pv[e][2]*wgt_sh[2*KP+kp]
                    + pv[e][3]*wgt_sh[3*KP+kp];
            dst[(k*CC+c)*TP + p] = v;
        }
    };
    auto gemm = [&](const float* wb, const float* sb){
        #pragma unroll
        for (int c=0;c<CC;c++){
            #pragma unroll
            for (int k=0;k<9;k++){
                float4 wv = *(const float4*)(wb + (c*9+k)*COUT + og*OCT);
                unsigned long long wd[OCT];
                wd[0] = f32x2_dup(wv.x); wd[1] = f32x2_dup(wv.y);
                wd[2] = f32x2_dup(wv.z); wd[3] = f32x2_dup(wv.w);
                const ulonglong2* sp = (const ulonglong2*)(sb + (k*CC+c)*TP + pg*PXT);
                ulonglong2 sa = sp[0], sb2 = sp[1];
                unsigned long long sv2[4] = {sa.x, sa.y, sb2.x, sb2.y};
                #pragma unroll
                for (int pp=0; pp<PXT/2; pp++)
                    #pragma unroll
                    for (int oc=0; oc<OCT; oc++)
                        fma_f32x2(acc[pp][oc], sv2[pp], wd[oc]);
            }
        }
    };

    stage_w(0, w_shA);
    prefetch(0);
    combine_store(sampA);
    cp_wait0();
    __syncthreads();

    for (int ch=0; ch<NCH; ch++){
        const float* wb = (ch & 1) ? w_shB : w_shA;
        const float* sb = (ch & 1) ? sampB : sampA;
        float* wn = (ch & 1) ? w_shA : w_shB;
        float* sn = (ch & 1) ? sampA : sampB;
        bool more = (ch+1 < NCH);
        if (more){
            stage_w(ch+1, wn);
            prefetch(ch+1);
        }
        gemm(wb, sb);
        if (more) combine_store(sn);
        cp_wait0();
        __syncthreads();
    }

    float* out_sh = smem;
    #pragma unroll
    for (int pp=0; pp<PXT/2; pp++)
        #pragma unroll
        for (int oc=0; oc<OCT; oc++){
            float lo, hi;
            f32x2_unpack(acc[pp][oc], lo, hi);
            out_sh[(og*OCT+oc)*TP + pg*PXT + pp*2 + 0] = lo;
            out_sh[(og*OCT+oc)*TP + pg*PXT + pp*2 + 1] = hi;
        }
    __syncthreads();
    for (int i=tid; i<COUT*TP; i+=256){
        int o = i>>6; int p = i & 63;
        float v = out_sh[i] + bias[o];
        out[((size_t)b*COUT + o)*HWn + rem + p] = fmaxf(v, 0.f);
    }
}

// ---------------------------------------------------------------------------
extern "C" void kernel_launch(void* const* d_in, const int* in_sizes, int n_in,
                              void* d_out, int out_size)
{
    (void)in_sizes; (void)n_in; (void)out_size;
    const float* x       = (const float*)d_in[0];
    const float* w_off1  = (const float*)d_in[1];
    const float* b_off1  = (const float*)d_in[2];
    const float* w_mask1 = (const float*)d_in[3];
    const float* b_mask1 = (const float*)d_in[4];
    const float* w1      = (const float*)d_in[5];
    const float* b1      = (const float*)d_in[6];
    const float* w_off2  = (const float*)d_in[7];
    const float* b_off2  = (const float*)d_in[8];
    const float* w_mask2 = (const float*)d_in[9];
    const float* b_mask2 = (const float*)d_in[10];
    const float* w2      = (const float*)d_in[11];
    const float* b2      = (const float*)d_in[12];
    float* out = (float*)d_out;

    float *p_off1, *p_mask1, *p_h, *p_off2, *p_mask2, *p_w1t, *p_w2t;
    cudaGetSymbolAddress((void**)&p_off1,  g_off1);
    cudaGetSymbolAddress((void**)&p_mask1, g_mask1);
    cudaGetSymbolAddress((void**)&p_h,     g_h);
    cudaGetSymbolAddress((void**)&p_off2,  g_off2);
    cudaGetSymbolAddress((void**)&p_mask2, g_mask2);
    cudaGetSymbolAddress((void**)&p_w1t,   g_w1t);
    cudaGetSymbolAddress((void**)&p_w2t,   g_w2t);

    constexpr int D2_SMEM = (8*576 + 2*4608 + 2*2304) * 4;  // 73728 B
    cudaFuncSetAttribute(deform2_kernel<64,128>,
                         cudaFuncAttributeMaxDynamicSharedMemorySize, D2_SMEM);

    wtrans_kernel<<<288, 256>>>(w1, w2, p_w1t, p_w2t);
    // Layer 1
    offmask_kernel<3,3><<<Bn*8*8, 512>>>(x, w_off1, b_off1, w_mask1, b_mask1,
                                         p_off1, p_mask1);
    deform_kernel<3,64,3,2><<<Bn*HWn/64, 256>>>(x, p_off1, p_mask1, p_w1t, b1, p_h);
    // Layer 2
    offmask_kernel<64,8><<<Bn*8*8, 512>>>(p_h, w_off2, b_off2, w_mask2, b_mask2,
                                          p_off2, p_mask2);
    deform2_kernel<64,128><<<Bn*HWn/64, 256, D2_SMEM>>>(p_h, p_off2, p_mask2,
                                                        p_w2t, b2, out);
}

// round 10
// speedup vs baseline: 1.0725x; 1.0725x over previous
#include <cuda_runtime.h>
#include <cstdint>
#include <math.h>

// Problem constants
#define Bn  4
#define Hn  128
#define Wn  128
#define HWn (Hn*Wn)

// Intermediate scratch (device globals: no allocation allowed)
__device__ float g_off1[Bn*18*HWn];
__device__ float g_mask1[Bn*9*HWn];
__device__ float g_h   [Bn*64*HWn];
__device__ float g_off2p [2*Bn*18*HWn];  // layer-2 offset partial sums (2 halves)
__device__ float g_mask2p[2*Bn*9*HWn];   // layer-2 mask logit partial sums
__device__ float g_w1t[3*9*64];     // w1 transposed: [c][k][o]
__device__ float g_w2t[64*9*128];   // w2 transposed: [c][k][o]

// ---------------------------------------------------------------------------
// f32x2 helpers (deform2 GEMM only — proven win there, loser in offmask)
// ---------------------------------------------------------------------------
__device__ __forceinline__ unsigned long long f32x2_dup(float w){
    unsigned long long d;
    asm("mov.b64 %0, {%1, %1};" : "=l"(d) : "r"(__float_as_uint(w)));
    return d;
}
__device__ __forceinline__ void f32x2_unpack(unsigned long long v, float& lo, float& hi){
    unsigned int a, b;
    asm("mov.b64 {%0, %1}, %2;" : "=r"(a), "=r"(b) : "l"(v));
    lo = __uint_as_float(a); hi = __uint_as_float(b);
}
__device__ __forceinline__ void fma_f32x2(unsigned long long& acc,
                                          unsigned long long a,
                                          unsigned long long b){
    asm("fma.rn.f32x2 %0, %1, %2, %0;" : "+l"(acc) : "l"(a), "l"(b));
}
__device__ __forceinline__ void cp_async16(unsigned int s, const void* g){
    asm volatile("cp.async.cg.shared.global [%0], [%1], 16;" :: "r"(s), "l"(g));
}
__device__ __forceinline__ void cp_commit(){
    asm volatile("cp.async.commit_group;");
}
__device__ __forceinline__ void cp_wait0(){
    asm volatile("cp.async.wait_group 0;");
}

// ---------------------------------------------------------------------------
// One-time weight transpose: w*t[(c*9+k)*COUT + o] = w[(o*CIN+c)*9 + k]
// ---------------------------------------------------------------------------
__global__ void wtrans_kernel(const float* __restrict__ w1, const float* __restrict__ w2,
                              float* __restrict__ w1t, float* __restrict__ w2t)
{
    int i = blockIdx.x*256 + threadIdx.x;
    if (i < 3*9*64){
        int o = i & 63; int ck = i >> 6; int c = ck/9, k = ck - 9*c;
        w1t[i] = w1[(o*3 + c)*9 + k];
    }
    if (i < 64*9*128){
        int o = i & 127; int ck = i >> 7; int c = ck/9, k = ck - 9*c;
        w2t[i] = w2[(o*64 + c)*9 + k];
    }
}

// ---------------------------------------------------------------------------
// Layer-1 offset/mask conv (round-4 scalar shape): 256 thr, 16x16 tile,
// full output incl. bias + sigmoid. CIN=3 (single chunk).
// ---------------------------------------------------------------------------
template<int CIN, int CC>
__global__ __launch_bounds__(256)
void offmask_kernel(const float* __restrict__ in,
                    const float* __restrict__ w_off, const float* __restrict__ b_off,
                    const float* __restrict__ w_mask, const float* __restrict__ b_mask,
                    float* __restrict__ off_out, float* __restrict__ mask_out)
{
    constexpr int NCH = CIN/CC;
    __shared__ float tile[CC][18][18];
    __shared__ __align__(16) float wsh[CC*9][28];

    int tid = threadIdx.x;
    int blk = blockIdx.x;
    int bx = blk & 7;
    int by = (blk >> 3) & 7;
    int b  = blk >> 6;
    int h0 = by*16, w0 = bx*16;
    int ty = tid >> 4, tx = tid & 15;

    float acc[28];
    #pragma unroll
    for (int i=0;i<28;i++) acc[i] = 0.f;

    for (int ch=0; ch<NCH; ch++){
        int c0 = ch*CC;
        for (int i=tid; i<CC*18*18; i+=256){
            int c = i/(18*18); int r = (i/18)%18; int col = i%18;
            int gy = h0-1+r, gx = w0-1+col;
            float v = 0.f;
            if (gy>=0 && gy<Hn && gx>=0 && gx<Wn)
                v = in[((b*CIN + c0+c)*Hn + gy)*Wn + gx];
            tile[c][r][col] = v;
        }
        for (int i=tid; i<CC*9; i+=256) wsh[i][27] = 0.f;
        for (int i=tid; i<CC*9*27; i+=256){
            int ck = i % (CC*9); int m = i / (CC*9);
            int c = ck/9, k = ck - c*9;
            wsh[ck][m] = (m < 18) ? __ldg(&w_off [(m*CIN + c0+c)*9 + k])
                                  : __ldg(&w_mask[((m-18)*CIN + c0+c)*9 + k]);
        }
        __syncthreads();
        #pragma unroll
        for (int c=0;c<CC;c++){
            float nb[9];
            #pragma unroll
            for (int ky=0;ky<3;ky++)
                #pragma unroll
                for (int kx=0;kx<3;kx++)
                    nb[ky*3+kx] = tile[c][ty+ky][tx+kx];
            #pragma unroll
            for (int k=0;k<9;k++){
                float v = nb[k];
                const float4* w4 = (const float4*)(&wsh[c*9+k][0]);
                #pragma unroll
                for (int mg=0; mg<7; mg++){
                    float4 wv = w4[mg];
                    acc[mg*4+0] = fmaf(v, wv.x, acc[mg*4+0]);
                    acc[mg*4+1] = fmaf(v, wv.y, acc[mg*4+1]);
                    acc[mg*4+2] = fmaf(v, wv.z, acc[mg*4+2]);
                    acc[mg*4+3] = fmaf(v, wv.w, acc[mg*4+3]);
                }
            }
        }
        __syncthreads();
    }
    int hw = (h0+ty)*Wn + (w0+tx);
    #pragma unroll
    for (int m=0;m<18;m++)
        off_out[(b*18+m)*HWn + hw] = acc[m] + b_off[m];
    #pragma unroll
    for (int m=0;m<9;m++){
        float v = acc[18+m] + b_mask[m];
        mask_out[(b*9+m)*HWn + hw] = 1.f/(1.f + expf(-v));
    }
}

// ---------------------------------------------------------------------------
// Layer-2 offset/mask conv, channel-split: grid 512, half = blk>>8 processes
// 4 of 8 channel chunks, writes RAW partial sums (no bias/sigmoid — consumer
// combines). Same per-thread inner loop as the proven round-4 scalar shape,
// 3 blocks/SM via launch_bounds.
// ---------------------------------------------------------------------------
template<int CIN, int CC>
__global__ __launch_bounds__(256, 3)
void offmask_part_kernel(const float* __restrict__ in,
                         const float* __restrict__ w_off,
                         const float* __restrict__ w_mask,
                         float* __restrict__ off_part, float* __restrict__ mask_part)
{
    constexpr int NCH  = CIN/CC;        // 8
    constexpr int NCHH = NCH/2;         // 4 chunks per half
    __shared__ float tile[CC][18][18];
    __shared__ __align__(16) float wsh[CC*9][28];

    int tid  = threadIdx.x;
    int blk  = blockIdx.x;
    int half = blk >> 8;
    int t    = blk & 255;
    int bx = t & 7;
    int by = (t >> 3) & 7;
    int b  = t >> 6;
    int h0 = by*16, w0 = bx*16;
    int ty = tid >> 4, tx = tid & 15;

    float acc[28];
    #pragma unroll
    for (int i=0;i<28;i++) acc[i] = 0.f;

    for (int ch = half*NCHH; ch < half*NCHH + NCHH; ch++){
        int c0 = ch*CC;
        for (int i=tid; i<CC*18*18; i+=256){
            int c = i/(18*18); int r = (i/18)%18; int col = i%18;
            int gy = h0-1+r, gx = w0-1+col;
            float v = 0.f;
            if (gy>=0 && gy<Hn && gx>=0 && gx<Wn)
                v = in[((b*CIN + c0+c)*Hn + gy)*Wn + gx];
            tile[c][r][col] = v;
        }
        for (int i=tid; i<CC*9; i+=256) wsh[i][27] = 0.f;
        for (int i=tid; i<CC*9*27; i+=256){
            int ck = i % (CC*9); int m = i / (CC*9);
            int c = ck/9, k = ck - c*9;
            wsh[ck][m] = (m < 18) ? __ldg(&w_off [(m*CIN + c0+c)*9 + k])
                                  : __ldg(&w_mask[((m-18)*CIN + c0+c)*9 + k]);
        }
        __syncthreads();
        #pragma unroll
        for (int c=0;c<CC;c++){
            float nb[9];
            #pragma unroll
            for (int ky=0;ky<3;ky++)
                #pragma unroll
                for (int kx=0;kx<3;kx++)
                    nb[ky*3+kx] = tile[c][ty+ky][tx+kx];
            #pragma unroll
            for (int k=0;k<9;k++){
                float v = nb[k];
                const float4* w4 = (const float4*)(&wsh[c*9+k][0]);
                #pragma unroll
                for (int mg=0; mg<7; mg++){
                    float4 wv = w4[mg];
                    acc[mg*4+0] = fmaf(v, wv.x, acc[mg*4+0]);
                    acc[mg*4+1] = fmaf(v, wv.y, acc[mg*4+1]);
                    acc[mg*4+2] = fmaf(v, wv.z, acc[mg*4+2]);
                    acc[mg*4+3] = fmaf(v, wv.w, acc[mg*4+3]);
                }
            }
        }
        __syncthreads();
    }

    // Raw partial sums; consumer adds halves + bias (+ sigmoid for mask).
    int hw = (h0+ty)*Wn + (w0+tx);
    #pragma unroll
    for (int m=0;m<18;m++)
        off_part[((half*Bn + b)*18 + m)*HWn + hw] = acc[m];
    #pragma unroll
    for (int m=0;m<9;m++)
        mask_part[((half*Bn + b)*9 + m)*HWn + hw] = acc[18+m];
}

// ---------------------------------------------------------------------------
// Layer-1 deformable conv (CIN=3): staging uses pre-transposed weights.
// ---------------------------------------------------------------------------
template<int CIN, int COUT, int CC, int OCT>
__global__ __launch_bounds__(256)
void deform_kernel(const float* __restrict__ in,
                   const float* __restrict__ off, const float* __restrict__ mask,
                   const float* __restrict__ wt, const float* __restrict__ bias,
                   float* __restrict__ out)
{
    constexpr int TP  = 64;
    constexpr int OG  = COUT/OCT;
    constexpr int NPG = 256/OG;
    constexpr int PXT = TP/NPG;
    constexpr int NCH = CIN/CC;
    constexpr int PARAMF = 5*9*TP;
    constexpr int WF = CC*9*COUT;
    constexpr int SF = 9*CC*TP;
    constexpr int MAINF = PARAMF + WF + SF;
    constexpr int OUTF  = COUT*TP;
    constexpr int SMEMF = (MAINF > OUTF) ? MAINF : OUTF;
    __shared__ __align__(16) float buf[SMEMF];

    int*   y0_sh  = (int*)buf;
    int*   x0_sh  = (int*)(buf + 9*TP);
    float* wy1_sh = buf + 2*9*TP;
    float* wx1_sh = buf + 3*9*TP;
    float* mm_sh  = buf + 4*9*TP;
    float* w_sh   = buf + PARAMF;
    float* samp_sh= buf + PARAMF + WF;

    int tid  = threadIdx.x;
    int base = blockIdx.x * TP;
    int b    = base / HWn;
    int rem  = base - b*HWn;
    int h    = rem / Wn;
    int w0   = rem - h*Wn;

    for (int s=tid; s<9*TP; s+=256){
        int p = s & (TP-1); int k = s/TP;
        int wpix = w0 + p;
        int hw = h*Wn + wpix;
        float dy = off[(b*18 + 2*k  )*HWn + hw];
        float dx = off[(b*18 + 2*k+1)*HWn + hw];
        float mm = mask[(b*9 + k)*HWn + hw];
        int ky = k/3, kx = k - ky*3;
        float py = dy + (float)(h - 1 + ky);
        float px = dx + (float)(wpix - 1 + kx);
        float fy = floorf(py), fx = floorf(px);
        y0_sh[s]  = (int)fy;
        x0_sh[s]  = (int)fx;
        wy1_sh[s] = py - fy;
        wx1_sh[s] = px - fx;
        mm_sh[s]  = mm;
    }

    float acc[PXT][OCT];
    #pragma unroll
    for (int i=0;i<PXT;i++)
        #pragma unroll
        for (int j=0;j<OCT;j++) acc[i][j] = 0.f;

    int og = tid % OG;
    int pg = tid / OG;

    __syncthreads();

    for (int ch=0; ch<NCH; ch++){
        int c0 = ch*CC;
        for (int i=tid; i<WF; i+=256)
            w_sh[i] = wt[ch*WF + i];
        for (int s=tid; s<9*CC*TP; s+=256){
            int p = s & (TP-1); int cc = (s/TP)%CC; int k = s/(TP*CC);
            int kp = k*TP + p;
            int y0 = y0_sh[kp], x0 = x0_sh[kp];
            float wy1 = wy1_sh[kp], wx1 = wx1_sh[kp];
            float wy0 = 1.f-wy1, wx0 = 1.f-wx1;
            const float* cp = in + (size_t)(b*CIN + c0+cc)*HWn;
            int y1 = y0+1, x1 = x0+1;
            bool vy0 = (unsigned)y0 < (unsigned)Hn;
            bool vy1 = (unsigned)y1 < (unsigned)Hn;
            bool vx0 = (unsigned)x0 < (unsigned)Wn;
            bool vx1 = (unsigned)x1 < (unsigned)Wn;
            float v = 0.f;
            if (vy0 && vx0) v = fmaf(cp[y0*Wn+x0], wy0*wx0, v);
            if (vy0 && vx1) v = fmaf(cp[y0*Wn+x1], wy0*wx1, v);
            if (vy1 && vx0) v = fmaf(cp[y1*Wn+x0], wy1*wx0, v);
            if (vy1 && vx1) v = fmaf(cp[y1*Wn+x1], wy1*wx1, v);
            samp_sh[(k*CC+cc)*TP + p] = v * mm_sh[kp];
        }
        __syncthreads();
        #pragma unroll
        for (int c=0;c<CC;c++){
            #pragma unroll
            for (int k=0;k<9;k++){
                float wv[OCT];
                const float* wp = w_sh + (c*9+k)*COUT + og*OCT;
                if constexpr (OCT == 4){
                    float4 t = *(const float4*)wp;
                    wv[0]=t.x; wv[1]=t.y; wv[2]=t.z; wv[3]=t.w;
                } else {
                    float2 t = *(const float2*)wp;
                    wv[0]=t.x; wv[1]=t.y;
                }
                const float* sp = samp_sh + (k*CC+c)*TP + pg*PXT;
                float4 s0 = *(const float4*)sp;
                float4 s1 = *(const float4*)(sp+4);
                float sv[8] = {s0.x,s0.y,s0.z,s0.w,s1.x,s1.y,s1.z,s1.w};
                #pragma unroll
                for (int px=0; px<PXT; px++)
                    #pragma unroll
                    for (int oc=0; oc<OCT; oc++)
                        acc[px][oc] = fmaf(sv[px], wv[oc], acc[px][oc]);
            }
        }
        __syncthreads();
    }

    float* out_sh = buf;
    #pragma unroll
    for (int px=0; px<PXT; px++)
        #pragma unroll
        for (int oc=0; oc<OCT; oc++)
            out_sh[(og*OCT+oc)*TP + pg*PXT + px] = acc[px][oc];
    __syncthreads();
    for (int i=tid; i<OUTF; i+=256){
        int o = i/TP; int p = i & (TP-1);
        float v = out_sh[i] + bias[o];
        out[((size_t)b*COUT + o)*HWn + rem + p] = fmaxf(v, 0.f);
    }
}

// ---------------------------------------------------------------------------
// Layer-2 deformable conv v4:
//   phase-0 combines the two offmask partial sums + bias and applies the
//   sigmoid (moved out of offmask). Rest unchanged (cp.async weights,
//   double-buffer, one barrier/chunk, f32x2 GEMM).
// ---------------------------------------------------------------------------
template<int CIN, int COUT>
__global__ __launch_bounds__(256, 2)
void deform2_kernel(const float* __restrict__ in,
                    const float* __restrict__ offp, const float* __restrict__ maskp,
                    const float* __restrict__ b_off, const float* __restrict__ b_mask,
                    const float* __restrict__ wt, const float* __restrict__ bias,
                    float* __restrict__ out)
{
    constexpr int TP  = 64;
    constexpr int CC  = 4;
    constexpr int NCH = CIN/CC;     // 16
    constexpr int OCT = 4;
    constexpr int PXT = 8;
    constexpr int KP  = 9*TP;       // 576
    constexpr int WF  = CC*9*COUT;  // 4608
    constexpr int SF  = 9*CC*TP;    // 2304
    constexpr int ELEMS = 9;
    extern __shared__ __align__(16) float smem[];

    int*   off_sh = (int*)smem;               // [4][KP]
    float* wgt_sh = smem + 4*KP;              // [4][KP]
    float* w_shA  = smem + 8*KP;              // [WF] x2
    float* w_shB  = w_shA + WF;
    float* sampA  = w_shB + WF;               // [SF] x2
    float* sampB  = sampA + SF;

    int tid  = threadIdx.x;
    int base = blockIdx.x * TP;
    int b    = base / HWn;
    int rem  = base - b*HWn;
    int h    = rem / Wn;
    int w0   = rem - h*Wn;

    for (int s=tid; s<KP; s+=256){
        int p = s & 63, k = s >> 6;
        int wpix = w0 + p;
        int hw = h*Wn + wpix;
        // combine the two channel-half partial sums + bias
        float dy = offp[(b*18 + 2*k  )*HWn + hw]
                 + offp[((Bn+b)*18 + 2*k  )*HWn + hw] + b_off[2*k];
        float dx = offp[(b*18 + 2*k+1)*HWn + hw]
                 + offp[((Bn+b)*18 + 2*k+1)*HWn + hw] + b_off[2*k+1];
        float ml = maskp[(b*9 + k)*HWn + hw]
                 + maskp[((Bn+b)*9 + k)*HWn + hw] + b_mask[k];
        float mm = 1.f/(1.f + expf(-ml));
        int ky = k/3, kx = k - ky*3;
        float py = dy + (float)(h - 1 + ky);
        float px = dx + (float)(wpix - 1 + kx);
        float fy = floorf(py), fx = floorf(px);
        int y0 = (int)fy, x0 = (int)fx;
        int y1 = y0+1, x1 = x0+1;
        float wy1 = py - fy, wx1 = px - fx;
        float wy0 = 1.f - wy1, wx0 = 1.f - wx1;
        bool vy0 = (unsigned)y0 < (unsigned)Hn;
        bool vy1 = (unsigned)y1 < (unsigned)Hn;
        bool vx0 = (unsigned)x0 < (unsigned)Wn;
        bool vx1 = (unsigned)x1 < (unsigned)Wn;
        int y0c = min(max(y0,0),Hn-1), y1c = min(max(y1,0),Hn-1);
        int x0c = min(max(x0,0),Wn-1), x1c = min(max(x1,0),Wn-1);
        off_sh[0*KP+s] = y0c*Wn + x0c;  wgt_sh[0*KP+s] = (vy0&&vx0) ? wy0*wx0*mm : 0.f;
        off_sh[1*KP+s] = y0c*Wn + x1c;  wgt_sh[1*KP+s] = (vy0&&vx1) ? wy0*wx1*mm : 0.f;
        off_sh[2*KP+s] = y1c*Wn + x0c;  wgt_sh[2*KP+s] = (vy1&&vx0) ? wy1*wx0*mm : 0.f;
        off_sh[3*KP+s] = y1c*Wn + x1c;  wgt_sh[3*KP+s] = (vy1&&vx1) ? wy1*wx1*mm : 0.f;
    }
    __syncthreads();

    const float* in_b = in + (size_t)b*CIN*HWn;
    int og = tid & 31;
    int pg = tid >> 5;

    unsigned long long acc[PXT/2][OCT];
    #pragma unroll
    for (int i=0;i<PXT/2;i++)
        #pragma unroll
        for (int j=0;j<OCT;j++) acc[i][j] = 0ULL;

    float pv[ELEMS][4];

    auto stage_w = [&](int ch, float* dst){
        unsigned int d = (unsigned int)__cvta_generic_to_shared(dst);
        const float4* src = (const float4*)(wt + ch*WF);
        #pragma unroll
        for (int j=0;j<5;j++){
            int i = tid + j*256;
            if (i < WF/4) cp_async16(d + i*16, src + i);
        }
        cp_commit();
    };
    auto prefetch = [&](int ch){
        int c0 = ch*CC;
        #pragma unroll
        for (int e=0;e<ELEMS;e++){
            int s = tid + e*256;
            int p = s & 63, c = (s>>6)&3, k = s>>8;
            int kp = (k<<6) + p;
            const float* cp = in_b + (size_t)(c0+c)*HWn;
            pv[e][0] = __ldg(cp + off_sh[0*KP+kp]);
            pv[e][1] = __ldg(cp + off_sh[1*KP+kp]);
            pv[e][2] = __ldg(cp + off_sh[2*KP+kp]);
            pv[e][3] = __ldg(cp + off_sh[3*KP+kp]);
        }
    };
    auto combine_store = [&](float* dst){
        #pragma unroll
        for (int e=0;e<ELEMS;e++){
            int s = tid + e*256;
            int p = s & 63, c = (s>>6)&3, k = s>>8;
            int kp = (k<<6) + p;
            float v = pv[e][0]*wgt_sh[0*KP+kp]
                    + pv[e][1]*wgt_sh[1*KP+kp]
                    + pv[e][2]*wgt_sh[2*KP+kp]
                    + pv[e][3]*wgt_sh[3*KP+kp];
            dst[(k*CC+c)*TP + p] = v;
        }
    };
    auto gemm = [&](const float* wb, const float* sb){
        #pragma unroll
        for (int c=0;c<CC;c++){
            #pragma unroll
            for (int k=0;k<9;k++){
                float4 wv = *(const float4*)(wb + (c*9+k)*COUT + og*OCT);
                unsigned long long wd[OCT];
                wd[0] = f32x2_dup(wv.x); wd[1] = f32x2_dup(wv.y);
                wd[2] = f32x2_dup(wv.z); wd[3] = f32x2_dup(wv.w);
                const ulonglong2* sp = (const ulonglong2*)(sb + (k*CC+c)*TP + pg*PXT);
                ulonglong2 sa = sp[0], sb2 = sp[1];
                unsigned long long sv2[4] = {sa.x, sa.y, sb2.x, sb2.y};
                #pragma unroll
                for (int pp=0; pp<PXT/2; pp++)
                    #pragma unroll
                    for (int oc=0; oc<OCT; oc++)
                        fma_f32x2(acc[pp][oc], sv2[pp], wd[oc]);
            }
        }
    };

    stage_w(0, w_shA);
    prefetch(0);
    combine_store(sampA);
    cp_wait0();
    __syncthreads();

    for (int ch=0; ch<NCH; ch++){
        const float* wb = (ch & 1) ? w_shB : w_shA;
        const float* sb = (ch & 1) ? sampB : sampA;
        float* wn = (ch & 1) ? w_shA : w_shB;
        float* sn = (ch & 1) ? sampA : sampB;
        bool more = (ch+1 < NCH);
        if (more){
            stage_w(ch+1, wn);
            prefetch(ch+1);
        }
        gemm(wb, sb);
        if (more) combine_store(sn);
        cp_wait0();
        __syncthreads();
    }

    float* out_sh = smem;
    #pragma unroll
    for (int pp=0; pp<PXT/2; pp++)
        #pragma unroll
        for (int oc=0; oc<OCT; oc++){
            float lo, hi;
            f32x2_unpack(acc[pp][oc], lo, hi);
            out_sh[(og*OCT+oc)*TP + pg*PXT + pp*2 + 0] = lo;
            out_sh[(og*OCT+oc)*TP + pg*PXT + pp*2 + 1] = hi;
        }
    __syncthreads();
    for (int i=tid; i<COUT*TP; i+=256){
        int o = i>>6; int p = i & 63;
        float v = out_sh[i] + bias[o];
        out[((size_t)b*COUT + o)*HWn + rem + p] = fmaxf(v, 0.f);
    }
}

// ---------------------------------------------------------------------------
extern "C" void kernel_launch(void* const* d_in, const int* in_sizes, int n_in,
                              void* d_out, int out_size)
{
    (void)in_sizes; (void)n_in; (void)out_size;
    const float* x       = (const float*)d_in[0];
    const float* w_off1  = (const float*)d_in[1];
    const float* b_off1  = (const float*)d_in[2];
    const float* w_mask1 = (const float*)d_in[3];
    const float* b_mask1 = (const float*)d_in[4];
    const float* w1      = (const float*)d_in[5];
    const float* b1      = (const float*)d_in[6];
    const float* w_off2  = (const float*)d_in[7];
    const float* b_off2  = (const float*)d_in[8];
    const float* w_mask2 = (const float*)d_in[9];
    const float* b_mask2 = (const float*)d_in[10];
    const float* w2      = (const float*)d_in[11];
    const float* b2      = (const float*)d_in[12];
    float* out = (float*)d_out;

    float *p_off1, *p_mask1, *p_h, *p_off2p, *p_mask2p, *p_w1t, *p_w2t;
    cudaGetSymbolAddress((void**)&p_off1,   g_off1);
    cudaGetSymbolAddress((void**)&p_mask1,  g_mask1);
    cudaGetSymbolAddress((void**)&p_h,      g_h);
    cudaGetSymbolAddress((void**)&p_off2p,  g_off2p);
    cudaGetSymbolAddress((void**)&p_mask2p, g_mask2p);
    cudaGetSymbolAddress((void**)&p_w1t,    g_w1t);
    cudaGetSymbolAddress((void**)&p_w2t,    g_w2t);

    constexpr int D2_SMEM = (8*576 + 2*4608 + 2*2304) * 4;  // 73728 B
    cudaFuncSetAttribute(deform2_kernel<64,128>,
                         cudaFuncAttributeMaxDynamicSharedMemorySize, D2_SMEM);

    wtrans_kernel<<<288, 256>>>(w1, w2, p_w1t, p_w2t);
    // Layer 1
    offmask_kernel<3,3><<<Bn*8*8, 256>>>(x, w_off1, b_off1, w_mask1, b_mask1,
                                         p_off1, p_mask1);
    deform_kernel<3,64,3,2><<<Bn*HWn/64, 256>>>(x, p_off1, p_mask1, p_w1t, b1, p_h);
    // Layer 2 (channel-split offmask; combine + sigmoid inside deform2)
    offmask_part_kernel<64,8><<<2*Bn*8*8, 256>>>(p_h, w_off2, w_mask2,
                                                 p_off2p, p_mask2p);
    deform2_kernel<64,128><<<Bn*HWn/64, 256, D2_SMEM>>>(p_h, p_off2p, p_mask2p,
                                                        b_off2, b_mask2,
                                                        p_w2t, b2, out);
}

// round 11
// speedup vs baseline: 1.1168x; 1.0414x over previous
#include <cuda_runtime.h>
#include <cstdint>
#include <math.h>

// Problem constants
#define Bn  4
#define Hn  128
#define Wn  128
#define HWn (Hn*Wn)

// Intermediate scratch (device globals: no allocation allowed)
__device__ float g_off1[Bn*18*HWn];
__device__ float g_mask1[Bn*9*HWn];
__device__ float g_h   [Bn*64*HWn];
__device__ float g_off2p [4*Bn*18*HWn];  // layer-2 offset partial sums (4 quarters)
__device__ float g_mask2p[4*Bn*9*HWn];   // layer-2 mask logit partial sums
__device__ float g_w1t[3*9*64];     // w1 transposed: [c][k][o]
__device__ float g_w2t[64*9*128];   // w2 transposed: [c][k][o]

// ---------------------------------------------------------------------------
// f32x2 helpers (deform2 GEMM only — proven win there, loser in offmask)
// ---------------------------------------------------------------------------
__device__ __forceinline__ unsigned long long f32x2_dup(float w){
    unsigned long long d;
    asm("mov.b64 %0, {%1, %1};" : "=l"(d) : "r"(__float_as_uint(w)));
    return d;
}
__device__ __forceinline__ void f32x2_unpack(unsigned long long v, float& lo, float& hi){
    unsigned int a, b;
    asm("mov.b64 {%0, %1}, %2;" : "=r"(a), "=r"(b) : "l"(v));
    lo = __uint_as_float(a); hi = __uint_as_float(b);
}
__device__ __forceinline__ void fma_f32x2(unsigned long long& acc,
                                          unsigned long long a,
                                          unsigned long long b){
    asm("fma.rn.f32x2 %0, %1, %2, %0;" : "+l"(acc) : "l"(a), "l"(b));
}
__device__ __forceinline__ void cp_async16(unsigned int s, const void* g){
    asm volatile("cp.async.cg.shared.global [%0], [%1], 16;" :: "r"(s), "l"(g));
}
__device__ __forceinline__ void cp_commit(){
    asm volatile("cp.async.commit_group;");
}
__device__ __forceinline__ void cp_wait0(){
    asm volatile("cp.async.wait_group 0;");
}

// ---------------------------------------------------------------------------
// One-time weight transpose: w*t[(c*9+k)*COUT + o] = w[(o*CIN+c)*9 + k]
// ---------------------------------------------------------------------------
__global__ void wtrans_kernel(const float* __restrict__ w1, const float* __restrict__ w2,
                              float* __restrict__ w1t, float* __restrict__ w2t)
{
    int i = blockIdx.x*256 + threadIdx.x;
    if (i < 3*9*64){
        int o = i & 63; int ck = i >> 6; int c = ck/9, k = ck - 9*c;
        w1t[i] = w1[(o*3 + c)*9 + k];
    }
    if (i < 64*9*128){
        int o = i & 127; int ck = i >> 7; int c = ck/9, k = ck - 9*c;
        w2t[i] = w2[(o*64 + c)*9 + k];
    }
}

// ---------------------------------------------------------------------------
// Layer-1 offset/mask conv (round-4 scalar shape): 256 thr, 16x16 tile,
// full output incl. bias + sigmoid. CIN=3 (single chunk).
// ---------------------------------------------------------------------------
template<int CIN, int CC>
__global__ __launch_bounds__(256)
void offmask_kernel(const float* __restrict__ in,
                    const float* __restrict__ w_off, const float* __restrict__ b_off,
                    const float* __restrict__ w_mask, const float* __restrict__ b_mask,
                    float* __restrict__ off_out, float* __restrict__ mask_out)
{
    constexpr int NCH = CIN/CC;
    __shared__ float tile[CC][18][18];
    __shared__ __align__(16) float wsh[CC*9][28];

    int tid = threadIdx.x;
    int blk = blockIdx.x;
    int bx = blk & 7;
    int by = (blk >> 3) & 7;
    int b  = blk >> 6;
    int h0 = by*16, w0 = bx*16;
    int ty = tid >> 4, tx = tid & 15;

    float acc[28];
    #pragma unroll
    for (int i=0;i<28;i++) acc[i] = 0.f;

    for (int ch=0; ch<NCH; ch++){
        int c0 = ch*CC;
        for (int i=tid; i<CC*18*18; i+=256){
            int c = i/(18*18); int r = (i/18)%18; int col = i%18;
            int gy = h0-1+r, gx = w0-1+col;
            float v = 0.f;
            if (gy>=0 && gy<Hn && gx>=0 && gx<Wn)
                v = in[((b*CIN + c0+c)*Hn + gy)*Wn + gx];
            tile[c][r][col] = v;
        }
        for (int i=tid; i<CC*9; i+=256) wsh[i][27] = 0.f;
        for (int i=tid; i<CC*9*27; i+=256){
            int ck = i % (CC*9); int m = i / (CC*9);
            int c = ck/9, k = ck - c*9;
            wsh[ck][m] = (m < 18) ? __ldg(&w_off [(m*CIN + c0+c)*9 + k])
                                  : __ldg(&w_mask[((m-18)*CIN + c0+c)*9 + k]);
        }
        __syncthreads();
        #pragma unroll
        for (int c=0;c<CC;c++){
            #pragma unroll
            for (int k=0;k<9;k++){
                int ky = k/3, kx = k - 3*ky;
                float v = tile[c][ty+ky][tx+kx];
                const float4* w4 = (const float4*)(&wsh[c*9+k][0]);
                #pragma unroll
                for (int mg=0; mg<7; mg++){
                    float4 wv = w4[mg];
                    acc[mg*4+0] = fmaf(v, wv.x, acc[mg*4+0]);
                    acc[mg*4+1] = fmaf(v, wv.y, acc[mg*4+1]);
                    acc[mg*4+2] = fmaf(v, wv.z, acc[mg*4+2]);
                    acc[mg*4+3] = fmaf(v, wv.w, acc[mg*4+3]);
                }
            }
        }
        __syncthreads();
    }
    int hw = (h0+ty)*Wn + (w0+tx);
    #pragma unroll
    for (int m=0;m<18;m++)
        off_out[(b*18+m)*HWn + hw] = acc[m] + b_off[m];
    #pragma unroll
    for (int m=0;m<9;m++){
        float v = acc[18+m] + b_mask[m];
        mask_out[(b*9+m)*HWn + hw] = 1.f/(1.f + expf(-v));
    }
}

// ---------------------------------------------------------------------------
// Layer-2 offset/mask conv, QUARTER channel-split: grid 1024, quarter=blk>>8
// processes 2 of 8 channel chunks, writes RAW partial sums. nb loads folded
// into k-loop (each used once) to cut live regs; launch_bounds(256,4) pushes
// residency to 4 blocks/SM (~32 warps).
// ---------------------------------------------------------------------------
template<int CIN, int CC>
__global__ __launch_bounds__(256, 4)
void offmask_part_kernel(const float* __restrict__ in,
                         const float* __restrict__ w_off,
                         const float* __restrict__ w_mask,
                         float* __restrict__ off_part, float* __restrict__ mask_part)
{
    constexpr int NCH  = CIN/CC;        // 8
    constexpr int NCHQ = NCH/4;         // 2 chunks per quarter
    __shared__ float tile[CC][18][18];
    __shared__ __align__(16) float wsh[CC*9][28];

    int tid  = threadIdx.x;
    int blk  = blockIdx.x;
    int quart= blk >> 8;                // 0..3
    int t    = blk & 255;
    int bx = t & 7;
    int by = (t >> 3) & 7;
    int b  = t >> 6;
    int h0 = by*16, w0 = bx*16;
    int ty = tid >> 4, tx = tid & 15;

    float acc[28];
    #pragma unroll
    for (int i=0;i<28;i++) acc[i] = 0.f;

    for (int ch = quart*NCHQ; ch < quart*NCHQ + NCHQ; ch++){
        int c0 = ch*CC;
        for (int i=tid; i<CC*18*18; i+=256){
            int c = i/(18*18); int r = (i/18)%18; int col = i%18;
            int gy = h0-1+r, gx = w0-1+col;
            float v = 0.f;
            if (gy>=0 && gy<Hn && gx>=0 && gx<Wn)
                v = in[((b*CIN + c0+c)*Hn + gy)*Wn + gx];
            tile[c][r][col] = v;
        }
        for (int i=tid; i<CC*9; i+=256) wsh[i][27] = 0.f;
        for (int i=tid; i<CC*9*27; i+=256){
            int ck = i % (CC*9); int m = i / (CC*9);
            int c = ck/9, k = ck - c*9;
            wsh[ck][m] = (m < 18) ? __ldg(&w_off [(m*CIN + c0+c)*9 + k])
                                  : __ldg(&w_mask[((m-18)*CIN + c0+c)*9 + k]);
        }
        __syncthreads();
        #pragma unroll
        for (int c=0;c<CC;c++){
            #pragma unroll
            for (int k=0;k<9;k++){
                int ky = k/3, kx = k - 3*ky;
                float v = tile[c][ty+ky][tx+kx];   // folded: each value used once
                const float4* w4 = (const float4*)(&wsh[c*9+k][0]);
                #pragma unroll
                for (int mg=0; mg<7; mg++){
                    float4 wv = w4[mg];
                    acc[mg*4+0] = fmaf(v, wv.x, acc[mg*4+0]);
                    acc[mg*4+1] = fmaf(v, wv.y, acc[mg*4+1]);
                    acc[mg*4+2] = fmaf(v, wv.z, acc[mg*4+2]);
                    acc[mg*4+3] = fmaf(v, wv.w, acc[mg*4+3]);
                }
            }
        }
        __syncthreads();
    }

    // Raw partial sums; consumer adds 4 quarters + bias (+ sigmoid for mask).
    int hw = (h0+ty)*Wn + (w0+tx);
    #pragma unroll
    for (int m=0;m<18;m++)
        off_part[((quart*Bn + b)*18 + m)*HWn + hw] = acc[m];
    #pragma unroll
    for (int m=0;m<9;m++)
        mask_part[((quart*Bn + b)*9 + m)*HWn + hw] = acc[18+m];
}

// ---------------------------------------------------------------------------
// Layer-1 deformable conv (CIN=3): staging uses pre-transposed weights.
// ---------------------------------------------------------------------------
template<int CIN, int COUT, int CC, int OCT>
__global__ __launch_bounds__(256)
void deform_kernel(const float* __restrict__ in,
                   const float* __restrict__ off, const float* __restrict__ mask,
                   const float* __restrict__ wt, const float* __restrict__ bias,
                   float* __restrict__ out)
{
    constexpr int TP  = 64;
    constexpr int OG  = COUT/OCT;
    constexpr int NPG = 256/OG;
    constexpr int PXT = TP/NPG;
    constexpr int NCH = CIN/CC;
    constexpr int PARAMF = 5*9*TP;
    constexpr int WF = CC*9*COUT;
    constexpr int SF = 9*CC*TP;
    constexpr int MAINF = PARAMF + WF + SF;
    constexpr int OUTF  = COUT*TP;
    constexpr int SMEMF = (MAINF > OUTF) ? MAINF : OUTF;
    __shared__ __align__(16) float buf[SMEMF];

    int*   y0_sh  = (int*)buf;
    int*   x0_sh  = (int*)(buf + 9*TP);
    float* wy1_sh = buf + 2*9*TP;
    float* wx1_sh = buf + 3*9*TP;
    float* mm_sh  = buf + 4*9*TP;
    float* w_sh   = buf + PARAMF;
    float* samp_sh= buf + PARAMF + WF;

    int tid  = threadIdx.x;
    int base = blockIdx.x * TP;
    int b    = base / HWn;
    int rem  = base - b*HWn;
    int h    = rem / Wn;
    int w0   = rem - h*Wn;

    for (int s=tid; s<9*TP; s+=256){
        int p = s & (TP-1); int k = s/TP;
        int wpix = w0 + p;
        int hw = h*Wn + wpix;
        float dy = off[(b*18 + 2*k  )*HWn + hw];
        float dx = off[(b*18 + 2*k+1)*HWn + hw];
        float mm = mask[(b*9 + k)*HWn + hw];
        int ky = k/3, kx = k - ky*3;
        float py = dy + (float)(h - 1 + ky);
        float px = dx + (float)(wpix - 1 + kx);
        float fy = floorf(py), fx = floorf(px);
        y0_sh[s]  = (int)fy;
        x0_sh[s]  = (int)fx;
        wy1_sh[s] = py - fy;
        wx1_sh[s] = px - fx;
        mm_sh[s]  = mm;
    }

    float acc[PXT][OCT];
    #pragma unroll
    for (int i=0;i<PXT;i++)
        #pragma unroll
        for (int j=0;j<OCT;j++) acc[i][j] = 0.f;

    int og = tid % OG;
    int pg = tid / OG;

    __syncthreads();

    for (int ch=0; ch<NCH; ch++){
        int c0 = ch*CC;
        for (int i=tid; i<WF; i+=256)
            w_sh[i] = wt[ch*WF + i];
        for (int s=tid; s<9*CC*TP; s+=256){
            int p = s & (TP-1); int cc = (s/TP)%CC; int k = s/(TP*CC);
            int kp = k*TP + p;
            int y0 = y0_sh[kp], x0 = x0_sh[kp];
            float wy1 = wy1_sh[kp], wx1 = wx1_sh[kp];
            float wy0 = 1.f-wy1, wx0 = 1.f-wx1;
            const float* cp = in + (size_t)(b*CIN + c0+cc)*HWn;
            int y1 = y0+1, x1 = x0+1;
            bool vy0 = (unsigned)y0 < (unsigned)Hn;
            bool vy1 = (unsigned)y1 < (unsigned)Hn;
            bool vx0 = (unsigned)x0 < (unsigned)Wn;
            bool vx1 = (unsigned)x1 < (unsigned)Wn;
            float v = 0.f;
            if (vy0 && vx0) v = fmaf(cp[y0*Wn+x0], wy0*wx0, v);
            if (vy0 && vx1) v = fmaf(cp[y0*Wn+x1], wy0*wx1, v);
            if (vy1 && vx0) v = fmaf(cp[y1*Wn+x0], wy1*wx0, v);
            if (vy1 && vx1) v = fmaf(cp[y1*Wn+x1], wy1*wx1, v);
            samp_sh[(k*CC+cc)*TP + p] = v * mm_sh[kp];
        }
        __syncthreads();
        #pragma unroll
        for (int c=0;c<CC;c++){
            #pragma unroll
            for (int k=0;k<9;k++){
                float wv[OCT];
                const float* wp = w_sh + (c*9+k)*COUT + og*OCT;
                if constexpr (OCT == 4){
                    float4 t = *(const float4*)wp;
                    wv[0]=t.x; wv[1]=t.y; wv[2]=t.z; wv[3]=t.w;
                } else {
                    float2 t = *(const float2*)wp;
                    wv[0]=t.x; wv[1]=t.y;
                }
                const float* sp = samp_sh + (k*CC+c)*TP + pg*PXT;
                float4 s0 = *(const float4*)sp;
                float4 s1 = *(const float4*)(sp+4);
                float sv[8] = {s0.x,s0.y,s0.z,s0.w,s1.x,s1.y,s1.z,s1.w};
                #pragma unroll
                for (int px=0; px<PXT; px++)
                    #pragma unroll
                    for (int oc=0; oc<OCT; oc++)
                        acc[px][oc] = fmaf(sv[px], wv[oc], acc[px][oc]);
            }
        }
        __syncthreads();
    }

    float* out_sh = buf;
    #pragma unroll
    for (int px=0; px<PXT; px++)
        #pragma unroll
        for (int oc=0; oc<OCT; oc++)
            out_sh[(og*OCT+oc)*TP + pg*PXT + px] = acc[px][oc];
    __syncthreads();
    for (int i=tid; i<OUTF; i+=256){
        int o = i/TP; int p = i & (TP-1);
        float v = out_sh[i] + bias[o];
        out[((size_t)b*COUT + o)*HWn + rem + p] = fmaxf(v, 0.f);
    }
}

// ---------------------------------------------------------------------------
// Layer-2 deformable conv v5:
//   phase-0 combines FOUR offmask partial sums + bias and applies the
//   sigmoid. Rest unchanged (cp.async weights, double-buffer, one
//   barrier/chunk, f32x2 GEMM).
// ---------------------------------------------------------------------------
template<int CIN, int COUT>
__global__ __launch_bounds__(256, 2)
void deform2_kernel(const float* __restrict__ in,
                    const float* __restrict__ offp, const float* __restrict__ maskp,
                    const float* __restrict__ b_off, const float* __restrict__ b_mask,
                    const float* __restrict__ wt, const float* __restrict__ bias,
                    float* __restrict__ out)
{
    constexpr int TP  = 64;
    constexpr int CC  = 4;
    constexpr int NCH = CIN/CC;     // 16
    constexpr int OCT = 4;
    constexpr int PXT = 8;
    constexpr int KP  = 9*TP;       // 576
    constexpr int WF  = CC*9*COUT;  // 4608
    constexpr int SF  = 9*CC*TP;    // 2304
    constexpr int ELEMS = 9;
    extern __shared__ __align__(16) float smem[];

    int*   off_sh = (int*)smem;               // [4][KP]
    float* wgt_sh = smem + 4*KP;              // [4][KP]
    float* w_shA  = smem + 8*KP;              // [WF] x2
    float* w_shB  = w_shA + WF;
    float* sampA  = w_shB + WF;               // [SF] x2
    float* sampB  = sampA + SF;

    int tid  = threadIdx.x;
    int base = blockIdx.x * TP;
    int b    = base / HWn;
    int rem  = base - b*HWn;
    int h    = rem / Wn;
    int w0   = rem - h*Wn;

    for (int s=tid; s<KP; s+=256){
        int p = s & 63, k = s >> 6;
        int wpix = w0 + p;
        int hw = h*Wn + wpix;
        // combine the four channel-quarter partial sums + bias
        float dy = b_off[2*k], dx = b_off[2*k+1], ml = b_mask[k];
        #pragma unroll
        for (int q=0;q<4;q++){
            dy += offp[((q*Bn+b)*18 + 2*k  )*HWn + hw];
            dx += offp[((q*Bn+b)*18 + 2*k+1)*HWn + hw];
            ml += maskp[((q*Bn+b)*9 + k)*HWn + hw];
        }
        float mm = 1.f/(1.f + expf(-ml));
        int ky = k/3, kx = k - ky*3;
        float py = dy + (float)(h - 1 + ky);
        float px = dx + (float)(wpix - 1 + kx);
        float fy = floorf(py), fx = floorf(px);
        int y0 = (int)fy, x0 = (int)fx;
        int y1 = y0+1, x1 = x0+1;
        float wy1 = py - fy, wx1 = px - fx;
        float wy0 = 1.f - wy1, wx0 = 1.f - wx1;
        bool vy0 = (unsigned)y0 < (unsigned)Hn;
        bool vy1 = (unsigned)y1 < (unsigned)Hn;
        bool vx0 = (unsigned)x0 < (unsigned)Wn;
        bool vx1 = (unsigned)x1 < (unsigned)Wn;
        int y0c = min(max(y0,0),Hn-1), y1c = min(max(y1,0),Hn-1);
        int x0c = min(max(x0,0),Wn-1), x1c = min(max(x1,0),Wn-1);
        off_sh[0*KP+s] = y0c*Wn + x0c;  wgt_sh[0*KP+s] = (vy0&&vx0) ? wy0*wx0*mm : 0.f;
        off_sh[1*KP+s] = y0c*Wn + x1c;  wgt_sh[1*KP+s] = (vy0&&vx1) ? wy0*wx1*mm : 0.f;
        off_sh[2*KP+s] = y1c*Wn + x0c;  wgt_sh[2*KP+s] = (vy1&&vx0) ? wy1*wx0*mm : 0.f;
        off_sh[3*KP+s] = y1c*Wn + x1c;  wgt_sh[3*KP+s] = (vy1&&vx1) ? wy1*wx1*mm : 0.f;
    }
    __syncthreads();

    const float* in_b = in + (size_t)b*CIN*HWn;
    int og = tid & 31;
    int pg = tid >> 5;

    unsigned long long acc[PXT/2][OCT];
    #pragma unroll
    for (int i=0;i<PXT/2;i++)
        #pragma unroll
        for (int j=0;j<OCT;j++) acc[i][j] = 0ULL;

    float pv[ELEMS][4];

    auto stage_w = [&](int ch, float* dst){
        unsigned int d = (unsigned int)__cvta_generic_to_shared(dst);
        const float4* src = (const float4*)(wt + ch*WF);
        #pragma unroll
        for (int j=0;j<5;j++){
            int i = tid + j*256;
            if (i < WF/4) cp_async16(d + i*16, src + i);
        }
        cp_commit();
    };
    auto prefetch = [&](int ch){
        int c0 = ch*CC;
        #pragma unroll
        for (int e=0;e<ELEMS;e++){
            int s = tid + e*256;
            int p = s & 63, c = (s>>6)&3, k = s>>8;
            int kp = (k<<6) + p;
            const float* cp = in_b + (size_t)(c0+c)*HWn;
            pv[e][0] = __ldg(cp + off_sh[0*KP+kp]);
            pv[e][1] = __ldg(cp + off_sh[1*KP+kp]);
            pv[e][2] = __ldg(cp + off_sh[2*KP+kp]);
            pv[e][3] = __ldg(cp + off_sh[3*KP+kp]);
        }
    };
    auto combine_store = [&](float* dst){
        #pragma unroll
        for (int e=0;e<ELEMS;e++){
            int s = tid + e*256;
            int p = s & 63, c = (s>>6)&3, k = s>>8;
            int kp = (k<<6) + p;
            float v = pv[e][0]*wgt_sh[0*KP+kp]
                    + pv[e][1]*wgt_sh[1*KP+kp]
                    + pv[e][2]*wgt_sh[2*KP+kp]
                    + pv[e][3]*wgt_sh[3*KP+kp];
            dst[(k*CC+c)*TP + p] = v;
        }
    };
    auto gemm = [&](const float* wb, const float* sb){
        #pragma unroll
        for (int c=0;c<CC;c++){
            #pragma unroll
            for (int k=0;k<9;k++){
                float4 wv = *(const float4*)(wb + (c*9+k)*COUT + og*OCT);
                unsigned long long wd[OCT];
                wd[0] = f32x2_dup(wv.x); wd[1] = f32x2_dup(wv.y);
                wd[2] = f32x2_dup(wv.z); wd[3] = f32x2_dup(wv.w);
                const ulonglong2* sp = (const ulonglong2*)(sb + (k*CC+c)*TP + pg*PXT);
                ulonglong2 sa = sp[0], sb2 = sp[1];
                unsigned long long sv2[4] = {sa.x, sa.y, sb2.x, sb2.y};
                #pragma unroll
                for (int pp=0; pp<PXT/2; pp++)
                    #pragma unroll
                    for (int oc=0; oc<OCT; oc++)
                        fma_f32x2(acc[pp][oc], sv2[pp], wd[oc]);
            }
        }
    };

    stage_w(0, w_shA);
    prefetch(0);
    combine_store(sampA);
    cp_wait0();
    __syncthreads();

    for (int ch=0; ch<NCH; ch++){
        const float* wb = (ch & 1) ? w_shB : w_shA;
        const float* sb = (ch & 1) ? sampB : sampA;
        float* wn = (ch & 1) ? w_shA : w_shB;
        float* sn = (ch & 1) ? sampA : sampB;
        bool more = (ch+1 < NCH);
        if (more){
            stage_w(ch+1, wn);
            prefetch(ch+1);
        }
        gemm(wb, sb);
        if (more) combine_store(sn);
        cp_wait0();
        __syncthreads();
    }

    float* out_sh = smem;
    #pragma unroll
    for (int pp=0; pp<PXT/2; pp++)
        #pragma unroll
        for (int oc=0; oc<OCT; oc++){
            float lo, hi;
            f32x2_unpack(acc[pp][oc], lo, hi);
            out_sh[(og*OCT+oc)*TP + pg*PXT + pp*2 + 0] = lo;
            out_sh[(og*OCT+oc)*TP + pg*PXT + pp*2 + 1] = hi;
        }
    __syncthreads();
    for (int i=tid; i<COUT*TP; i+=256){
        int o = i>>6; int p = i & 63;
        float v = out_sh[i] + bias[o];
        out[((size_t)b*COUT + o)*HWn + rem + p] = fmaxf(v, 0.f);
    }
}

// ---------------------------------------------------------------------------
extern "C" void kernel_launch(void* const* d_in, const int* in_sizes, int n_in,
                              void* d_out, int out_size)
{
    (void)in_sizes; (void)n_in; (void)out_size;
    const float* x       = (const float*)d_in[0];
    const float* w_off1  = (const float*)d_in[1];
    const float* b_off1  = (const float*)d_in[2];
    const float* w_mask1 = (const float*)d_in[3];
    const float* b_mask1 = (const float*)d_in[4];
    const float* w1      = (const float*)d_in[5];
    const float* b1      = (const float*)d_in[6];
    const float* w_off2  = (const float*)d_in[7];
    const float* b_off2  = (const float*)d_in[8];
    const float* w_mask2 = (const float*)d_in[9];
    const float* b_mask2 = (const float*)d_in[10];
    const float* w2      = (const float*)d_in[11];
    const float* b2      = (const float*)d_in[12];
    float* out = (float*)d_out;

    float *p_off1, *p_mask1, *p_h, *p_off2p, *p_mask2p, *p_w1t, *p_w2t;
    cudaGetSymbolAddress((void**)&p_off1,   g_off1);
    cudaGetSymbolAddress((void**)&p_mask1,  g_mask1);
    cudaGetSymbolAddress((void**)&p_h,      g_h);
    cudaGetSymbolAddress((void**)&p_off2p,  g_off2p);
    cudaGetSymbolAddress((void**)&p_mask2p, g_mask2p);
    cudaGetSymbolAddress((void**)&p_w1t,    g_w1t);
    cudaGetSymbolAddress((void**)&p_w2t,    g_w2t);

    constexpr int D2_SMEM = (8*576 + 2*4608 + 2*2304) * 4;  // 73728 B
    cudaFuncSetAttribute(deform2_kernel<64,128>,
                         cudaFuncAttributeMaxDynamicSharedMemorySize, D2_SMEM);

    wtrans_kernel<<<288, 256>>>(w1, w2, p_w1t, p_w2t);
    // Layer 1
    offmask_kernel<3,3><<<Bn*8*8, 256>>>(x, w_off1, b_off1, w_mask1, b_mask1,
                                         p_off1, p_mask1);
    deform_kernel<3,64,3,2><<<Bn*HWn/64, 256>>>(x, p_off1, p_mask1, p_w1t, b1, p_h);
    // Layer 2 (quarter channel-split offmask; combine + sigmoid inside deform2)
    offmask_part_kernel<64,8><<<4*Bn*8*8, 256>>>(p_h, w_off2, w_mask2,
                                                 p_off2p, p_mask2p);
    deform2_kernel<64,128><<<Bn*HWn/64, 256, D2_SMEM>>>(p_h, p_off2p, p_mask2p,
                                                        b_off2, b_mask2,
                                                        p_w2t, b2, out);
}